// round 2
// baseline (speedup 1.0000x reference)
#include <cuda_runtime.h>

#define N_NODES 500000
#define N_EDGES 1250000
#define N_SUB   50000
#define N_GRAPH 64
#define NSCANB  489   // ceil(N_NODES/1024)

typedef unsigned long long u64;

// ---------------- scratch (device globals; no allocation allowed) -----------
__device__ float g_x[N_NODES * 64];    // node features
__device__ float g_m[N_NODES * 64];    // messages
__device__ float g_agg[N_NODES * 64];  // aggregated
__device__ float g_u[4 * 100 * 64];    // fused table: ze@Wright^T + b (layers 1..4)
__device__ float g_Bm[4 * 64 * 64];    // fused weight: Wleft^T @ G
__device__ float g_v[4 * 100 * 64];    // fused table: u @ G
__device__ float g_t0m[100 * 64];      // fused table: ztab0 @ G0 (layer 0)
__device__ float g_gsum[64 * 64];      // graph pooled sums
// CSR scratch
__device__ int g_deg[N_NODES];
__device__ int g_tmpoff[N_NODES];
__device__ int g_off[N_NODES + 1];
__device__ int g_cur[N_NODES];
__device__ int g_ssrc[N_EDGES];        // src ids sorted by dst
__device__ int g_bsum[NSCANB];

// ---------------- helpers ---------------------------------------------------
__device__ __forceinline__ u64 fma2(u64 a, u64 b, u64 c) {
    u64 d;
    asm("fma.rn.f32x2 %0, %1, %2, %3;" : "=l"(d) : "l"(a), "l"(b), "l"(c));
    return d;
}
__device__ __forceinline__ float red2(u64 v) {
    float a, b;
    asm("mov.b64 {%0, %1}, %2;" : "=f"(a), "=f"(b) : "l"(v));
    return a + b;
}
__device__ __forceinline__ float f2lo(u64 v) {
    float a, b;
    asm("mov.b64 {%0, %1}, %2;" : "=f"(a), "=f"(b) : "l"(v));
    return a;
}
__device__ __forceinline__ float f2hi(u64 v) {
    float a, b;
    asm("mov.b64 {%0, %1}, %2;" : "=f"(a), "=f"(b) : "l"(v));
    return b;
}
__device__ __forceinline__ float sigm(float x)  { return __fdividef(1.0f, 1.0f + __expf(-x)); }
__device__ __forceinline__ float tanh_(float x) { return __fdividef(2.0f, 1.0f + __expf(-2.0f * x)) - 1.0f; }
__device__ __forceinline__ float elu_(float x)  { return x > 0.0f ? x : (__expf(x) - 1.0f); }

// ---------------- CSR build --------------------------------------------------
__global__ void k_zero_deg() {
    int i = blockIdx.x * 256 + threadIdx.x;
    if (i < N_NODES) g_deg[i] = 0;
}
__global__ void k_hist(const int* __restrict__ dst) {
    int e = blockIdx.x * 256 + threadIdx.x;
    if (e < N_EDGES) atomicAdd(&g_deg[__ldg(dst + e)], 1);
}
__global__ void k_scan1() {
    __shared__ int sh[256];
    int b = blockIdx.x, t = threadIdx.x;
    int base = b * 1024 + t * 4;
    int v[4], s = 0;
    #pragma unroll
    for (int i = 0; i < 4; i++) {
        v[i] = (base + i < N_NODES) ? g_deg[base + i] : 0;
        s += v[i];
    }
    sh[t] = s;
    __syncthreads();
    for (int o = 1; o < 256; o <<= 1) {
        int x = (t >= o) ? sh[t - o] : 0;
        __syncthreads();
        sh[t] += x;
        __syncthreads();
    }
    int run = sh[t] - s;
    #pragma unroll
    for (int i = 0; i < 4; i++) {
        if (base + i < N_NODES) g_tmpoff[base + i] = run;
        run += v[i];
    }
    if (t == 255) g_bsum[b] = sh[255];
}
__global__ void k_scan2() {
    __shared__ int sh[512];
    int t = threadIdx.x;
    int v = (t < NSCANB) ? g_bsum[t] : 0;
    sh[t] = v;
    __syncthreads();
    for (int o = 1; o < 512; o <<= 1) {
        int x = (t >= o) ? sh[t - o] : 0;
        __syncthreads();
        sh[t] += x;
        __syncthreads();
    }
    if (t < NSCANB) g_bsum[t] = sh[t] - v;  // exclusive
}
__global__ void k_scan3() {
    int i = blockIdx.x * 256 + threadIdx.x;
    if (i < N_NODES) {
        int o = g_tmpoff[i] + g_bsum[i >> 10];
        g_off[i] = o;
        g_cur[i] = o;
    }
    if (i == 0) g_off[N_NODES] = N_EDGES;
}
__global__ void k_place(const int* __restrict__ src, const int* __restrict__ dst) {
    int e = blockIdx.x * 256 + threadIdx.x;
    if (e < N_EDGES) {
        int d = __ldg(dst + e);
        int pos = atomicAdd(&g_cur[d], 1);
        g_ssrc[pos] = __ldg(src + e);
    }
}

// ---------------- init / precompute ------------------------------------------
__global__ void k_zero_gsum() {
    int i = blockIdx.x * 256 + threadIdx.x;
    if (i < 4096) g_gsum[i] = 0.f;
}

__global__ void k_pre1(const float* __restrict__ ztab, const float* __restrict__ tfW,
                       const float* __restrict__ tfb, const float* __restrict__ ggcW) {
    int i = blockIdx.x * blockDim.x + threadIdx.x;
    if (i < 25600) {
        int j = i / 6400, r = (i % 6400) / 64, o = i % 64;
        const float* zt = ztab + (j + 1) * 6400 + r * 64;
        const float* w  = tfW + j * 8192 + o * 128 + 64;
        float acc = tfb[j * 64 + o];
        #pragma unroll
        for (int k = 0; k < 64; k++) acc += zt[k] * w[k];
        g_u[i] = acc;
    } else if (i < 41984) {
        int ii = i - 25600;
        int j = ii / 4096, o = (ii % 4096) / 64, k = ii % 64;
        const float* g = ggcW + (j + 1) * 4096 + o;
        const float* w = tfW + j * 8192 + k;
        float acc = 0.f;
        #pragma unroll
        for (int t = 0; t < 64; t++) acc += w[t * 128] * g[t * 64];
        g_Bm[ii] = acc;
    } else if (i < 48384) {
        int ii = i - 41984;
        int r = ii / 64, o = ii % 64;
        float acc = 0.f;
        #pragma unroll
        for (int k = 0; k < 64; k++) acc += ztab[r * 64 + k] * ggcW[k * 64 + o];
        g_t0m[ii] = acc;
    }
}

__global__ void k_pre2(const float* __restrict__ ggcW) {
    int i = blockIdx.x * blockDim.x + threadIdx.x;
    if (i >= 25600) return;
    int j = i / 6400, r = (i % 6400) / 64, o = i % 64;
    const float* urow = g_u + j * 6400 + r * 64;
    const float* g = ggcW + (j + 1) * 4096 + o;
    float acc = 0.f;
    #pragma unroll
    for (int t = 0; t < 64; t++) acc += urow[t] * g[t * 64];
    g_v[i] = acc;
}

// ---------------- layer 0: pure lookups --------------------------------------
__global__ void k_layer0(const int* __restrict__ z, const float* __restrict__ ztab) {
    int idx = blockIdx.x * 256 + threadIdx.x;  // N_NODES*16
    int n = idx >> 4, c = idx & 15;
    int r = __ldg(z + n);
    float4 a = ((const float4*)(ztab + r * 64))[c];
    ((float4*)(g_x + (size_t)n * 64))[c] = a;
    float4 b = ((const float4*)(g_t0m + r * 64))[c];
    ((float4*)(g_m + (size_t)n * 64))[c] = b;
}

// ---------------- layers 1..4 pre: xnew = x@Wl^T + u[z];  m = xnew@G fused ----
__global__ void __launch_bounds__(256) k_pre(const int* __restrict__ z,
                                             const float* __restrict__ tfW, int j) {
    __shared__ float sW[4096];  // tfW[j][o][0:64]
    __shared__ float sB[4096];  // B[j][o][k]
    int tid = threadIdx.x;
    for (int i = tid; i < 4096; i += 256) {
        int o = i >> 6, k = i & 63;
        sW[i] = tfW[j * 8192 + o * 128 + k];
        sB[i] = g_Bm[j * 4096 + i];
    }
    __syncthreads();
    int n = blockIdx.x * 256 + tid;
    if (n >= N_NODES) return;

    ulonglong2 X2[16];
    {
        const ulonglong2* xr = (const ulonglong2*)(g_x + (size_t)n * 64);
        #pragma unroll
        for (int i = 0; i < 16; i++) X2[i] = xr[i];
    }
    int zr = __ldg(z + n);
    const float* urow = g_u + j * 6400 + zr * 64;
    const float* vrow = g_v + j * 6400 + zr * 64;
    float4* xout = (float4*)(g_x + (size_t)n * 64);
    float4* mout = (float4*)(g_m + (size_t)n * 64);

    #pragma unroll 1
    for (int o4 = 0; o4 < 16; o4++) {
        int o = o4 * 4;
        const ulonglong2* w0 = (const ulonglong2*)(sW + o * 64);
        const ulonglong2* w1 = (const ulonglong2*)(sW + (o + 1) * 64);
        const ulonglong2* w2 = (const ulonglong2*)(sW + (o + 2) * 64);
        const ulonglong2* w3 = (const ulonglong2*)(sW + (o + 3) * 64);
        const ulonglong2* b0 = (const ulonglong2*)(sB + o * 64);
        const ulonglong2* b1 = (const ulonglong2*)(sB + (o + 1) * 64);
        const ulonglong2* b2 = (const ulonglong2*)(sB + (o + 2) * 64);
        const ulonglong2* b3 = (const ulonglong2*)(sB + (o + 3) * 64);
        u64 ax0 = 0, ax1 = 0, ax2 = 0, ax3 = 0;
        u64 am0 = 0, am1 = 0, am2 = 0, am3 = 0;
        #pragma unroll
        for (int k = 0; k < 16; k++) {
            ulonglong2 x = X2[k];
            ulonglong2 t;
            t = w0[k]; ax0 = fma2(x.x, t.x, ax0); ax0 = fma2(x.y, t.y, ax0);
            t = w1[k]; ax1 = fma2(x.x, t.x, ax1); ax1 = fma2(x.y, t.y, ax1);
            t = w2[k]; ax2 = fma2(x.x, t.x, ax2); ax2 = fma2(x.y, t.y, ax2);
            t = w3[k]; ax3 = fma2(x.x, t.x, ax3); ax3 = fma2(x.y, t.y, ax3);
            t = b0[k]; am0 = fma2(x.x, t.x, am0); am0 = fma2(x.y, t.y, am0);
            t = b1[k]; am1 = fma2(x.x, t.x, am1); am1 = fma2(x.y, t.y, am1);
            t = b2[k]; am2 = fma2(x.x, t.x, am2); am2 = fma2(x.y, t.y, am2);
            t = b3[k]; am3 = fma2(x.x, t.x, am3); am3 = fma2(x.y, t.y, am3);
        }
        float4 rx, rm;
        rx.x = red2(ax0) + __ldg(urow + o);
        rx.y = red2(ax1) + __ldg(urow + o + 1);
        rx.z = red2(ax2) + __ldg(urow + o + 2);
        rx.w = red2(ax3) + __ldg(urow + o + 3);
        rm.x = red2(am0) + __ldg(vrow + o);
        rm.y = red2(am1) + __ldg(vrow + o + 1);
        rm.z = red2(am2) + __ldg(vrow + o + 2);
        rm.w = red2(am3) + __ldg(vrow + o + 3);
        xout[o4] = rx;
        mout[o4] = rm;
    }
}

// ---------------- CSR gather: agg[n] = sum_{e: dst==n} m[src[e]] --------------
__global__ void k_gather() {
    int idx = blockIdx.x * 256 + threadIdx.x;  // N_NODES*16
    int n = idx >> 4, c = idx & 15;
    int e0 = __ldg(&g_off[n]), e1 = __ldg(&g_off[n + 1]);
    float4 acc = make_float4(0.f, 0.f, 0.f, 0.f);
    for (int e = e0; e < e1; e++) {
        int s = __ldg(&g_ssrc[e]);
        float4 v = ((const float4*)(g_m + (size_t)s * 64))[c];
        acc.x += v.x; acc.y += v.y; acc.z += v.z; acc.w += v.w;
    }
    ((float4*)(g_agg + (size_t)n * 64))[c] = acc;
}

// ---------------- GRU cell update ---------------------------------------------
__global__ void __launch_bounds__(256) k_gru(const float* __restrict__ wih,
                                             const float* __restrict__ whh,
                                             const float* __restrict__ bih,
                                             const float* __restrict__ bhh) {
    extern __shared__ float sm[];
    float* sWih = sm;            // 192*64
    float* sWhh = sm + 12288;    // 192*64
    float* sb   = sm + 24576;    // 192 bih | 192 bhh
    int tid = threadIdx.x;
    for (int i = tid; i < 12288; i += 256) {
        sWih[i] = wih[i];
        sWhh[i] = whh[i];
    }
    if (tid < 192) {
        sb[tid] = bih[tid];
        sb[192 + tid] = bhh[tid];
    }
    __syncthreads();
    int n = blockIdx.x * 256 + tid;
    if (n >= N_NODES) return;

    ulonglong2 A2[16], H2[16];
    {
        const ulonglong2* ar = (const ulonglong2*)(g_agg + (size_t)n * 64);
        const ulonglong2* hr = (const ulonglong2*)(g_x + (size_t)n * 64);
        #pragma unroll
        for (int i = 0; i < 16; i++) A2[i] = ar[i];
        #pragma unroll
        for (int i = 0; i < 16; i++) H2[i] = hr[i];
    }
    float4* xout = (float4*)(g_x + (size_t)n * 64);

    #pragma unroll 1
    for (int d4 = 0; d4 < 16; d4++) {
        float4 out;
        float* op = &out.x;
        ulonglong2 hold = H2[d4];
        #pragma unroll
        for (int q = 0; q < 4; q++) {
            int d = d4 * 4 + q;
            const ulonglong2* wr = (const ulonglong2*)(sWih + d * 64);
            const ulonglong2* wz = wr + 1024;
            const ulonglong2* wn = wr + 2048;
            const ulonglong2* vr = (const ulonglong2*)(sWhh + d * 64);
            const ulonglong2* vz = vr + 1024;
            const ulonglong2* vn = vr + 2048;
            u64 air = 0, aiz = 0, ain = 0, ahr = 0, ahz = 0, ahn = 0;
            #pragma unroll
            for (int k = 0; k < 16; k++) {
                ulonglong2 a = A2[k], h = H2[k];
                ulonglong2 t;
                t = wr[k]; air = fma2(a.x, t.x, air); air = fma2(a.y, t.y, air);
                t = wz[k]; aiz = fma2(a.x, t.x, aiz); aiz = fma2(a.y, t.y, aiz);
                t = wn[k]; ain = fma2(a.x, t.x, ain); ain = fma2(a.y, t.y, ain);
                t = vr[k]; ahr = fma2(h.x, t.x, ahr); ahr = fma2(h.y, t.y, ahr);
                t = vz[k]; ahz = fma2(h.x, t.x, ahz); ahz = fma2(h.y, t.y, ahz);
                t = vn[k]; ahn = fma2(h.x, t.x, ahn); ahn = fma2(h.y, t.y, ahn);
            }
            float r  = sigm(red2(air) + sb[d] + red2(ahr) + sb[192 + d]);
            float u  = sigm(red2(aiz) + sb[64 + d] + red2(ahz) + sb[256 + d]);
            float nn = tanh_(red2(ain) + sb[128 + d] + r * (red2(ahn) + sb[320 + d]));
            u64 hv = (q >= 2) ? hold.y : hold.x;
            float hd = (q & 1) ? f2hi(hv) : f2lo(hv);
            op[q] = (1.0f - u) * nn + u * hd;
        }
        xout[d4] = out;
    }
}

// ---------------- pooling (node -> graph, sums compose) -----------------------
__global__ void k_pool(const int* __restrict__ n2s, const int* __restrict__ s2g) {
    int idx = blockIdx.x * 256 + threadIdx.x;  // N_NODES*16
    int n = idx >> 4, c = idx & 15;
    int g = __ldg(s2g + __ldg(n2s + n));
    float4 v = ((const float4*)(g_x + (size_t)n * 64))[c];
    float* o = g_gsum + g * 64 + c * 4;
    atomicAdd(o + 0, v.x);
    atomicAdd(o + 1, v.y);
    atomicAdd(o + 2, v.z);
    atomicAdd(o + 3, v.w);
}

// ---------------- MLP head ----------------------------------------------------
__global__ void k_head(const float* __restrict__ w1, const float* __restrict__ b1,
                       const float* __restrict__ w2, const float* __restrict__ b2,
                       const float* __restrict__ w3, const float* __restrict__ b3,
                       float* __restrict__ out) {
    int g = threadIdx.x;
    if (g >= 64) return;
    const float* h0 = g_gsum + g * 64;
    float h1[32];
    #pragma unroll 4
    for (int o = 0; o < 32; o++) {
        float acc = b1[o];
        #pragma unroll
        for (int k = 0; k < 64; k++) acc += h0[k] * w1[o * 64 + k];
        h1[o] = elu_(acc);
    }
    float h2[16];
    #pragma unroll
    for (int p = 0; p < 16; p++) {
        float acc = b2[p];
        #pragma unroll
        for (int o = 0; o < 32; o++) acc += h1[o] * w2[p * 32 + o];
        h2[p] = elu_(acc);
    }
    float acc = b3[0];
    #pragma unroll
    for (int q = 0; q < 16; q++) acc += h2[q] * w3[q];
    out[g] = acc;
}

// ---------------- launch -------------------------------------------------------
extern "C" void kernel_launch(void* const* d_in, const int* in_sizes, int n_in,
                              void* d_out, int out_size) {
    const int*   z    = (const int*)d_in[0];
    const int*   ei   = (const int*)d_in[1];
    const int*   n2s  = (const int*)d_in[2];
    const int*   s2g  = (const int*)d_in[3];
    const float* ztab = (const float*)d_in[4];
    const float* tfW  = (const float*)d_in[5];
    const float* tfb  = (const float*)d_in[6];
    const float* ggcW = (const float*)d_in[7];
    const float* wih  = (const float*)d_in[8];
    const float* whh  = (const float*)d_in[9];
    const float* bih  = (const float*)d_in[10];
    const float* bhh  = (const float*)d_in[11];
    const float* w1   = (const float*)d_in[12];
    const float* b1   = (const float*)d_in[13];
    const float* w2   = (const float*)d_in[14];
    const float* b2   = (const float*)d_in[15];
    const float* w3   = (const float*)d_in[16];
    const float* b3   = (const float*)d_in[17];
    const int* src = ei;
    const int* dst = ei + N_EDGES;

    cudaFuncSetAttribute(k_gru, cudaFuncAttributeMaxDynamicSharedMemorySize, 100352);

    const int NB  = (N_NODES + 255) / 256;   // 1954
    const int EB  = (N_EDGES + 255) / 256;   // 4883

    // CSR build (by dst)
    k_zero_deg<<<NB, 256>>>();
    k_hist<<<EB, 256>>>(dst);
    k_scan1<<<NSCANB, 256>>>();
    k_scan2<<<1, 512>>>();
    k_scan3<<<NB, 256>>>();
    k_place<<<EB, 256>>>(src, dst);

    // precompute fused tables + layer 0
    k_pre1<<<189, 256>>>(ztab, tfW, tfb, ggcW);
    k_pre2<<<100, 256>>>(ggcW);
    k_layer0<<<31250, 256>>>(z, ztab);

    for (int l = 0; l < 5; l++) {
        if (l > 0) k_pre<<<NB, 256>>>(z, tfW, l - 1);
        k_gather<<<31250, 256>>>();
        k_gru<<<NB, 256, 99840>>>(wih + l * 12288, whh + l * 12288,
                                  bih + l * 192, bhh + l * 192);
    }

    k_zero_gsum<<<16, 256>>>();
    k_pool<<<31250, 256>>>(n2s, s2g);
    k_head<<<1, 64>>>(w1, b1, w2, b2, w3, b3, (float*)d_out);
}